// round 8
// baseline (speedup 1.0000x reference)
#include <cuda_runtime.h>
#include <cuda_fp16.h>
#include <cstdint>

#define NNODES_MAX 100000
#define NEDGES_MAX 2000000
#define NFEAT 128

// Scratch (allocation-free rule: __device__ globals)
__device__ __half2 g_hh[(size_t)NNODES_MAX * (NFEAT / 2)];  // h' = (x@W)*dinv, fp16
__device__ float g_dinv[NNODES_MAX];
__device__ int   g_cnt[NNODES_MAX];
__device__ int   g_scan[NNODES_MAX];
__device__ int   g_part[512];
__device__ int   g_off[NNODES_MAX];
__device__ int   g_cursor[NNODES_MAX];
__device__ int   g_csr[NEDGES_MAX];

// ---------------------------------------------------------------------------
__global__ void k_zero_cnt(int n) {
    int i = blockIdx.x * blockDim.x + threadIdx.x;
    if (i < n) g_cnt[i] = 0;
}

__global__ void k_count4(const int* __restrict__ ei, int E) {
    int e4 = blockIdx.x * blockDim.x + threadIdx.x;
    if (e4 * 4 >= E) return;
    int4 d = ((const int4*)(ei + E))[e4];
    atomicAdd(&g_cnt[d.x], 1);
    atomicAdd(&g_cnt[d.y], 1);
    atomicAdd(&g_cnt[d.z], 1);
    atomicAdd(&g_cnt[d.w], 1);
}
__global__ void k_count1(const int* __restrict__ ei, int E) {
    int e = blockIdx.x * blockDim.x + threadIdx.x;
    if (e < E) atomicAdd(&g_cnt[ei[E + e]], 1);
}

__global__ void k_dinv(int n) {
    int i = blockIdx.x * blockDim.x + threadIdx.x;
    if (i < n) g_dinv[i] = rsqrtf((float)g_cnt[i] + 1.0f);
}

// ---------------------------------------------------------------------------
// GEMM h' = (x @ W) * dinv  — full-K smem residency, ONE __syncthreads,
// barrier-free mainloop. A row-major stride 130 (half-warp broadcast groups on
// distinct banks), B row-major 128 (conflict-free split-N LDS.128).
#define BM 64
#define ASTRIDE 130
#define TM 8

__global__ __launch_bounds__(128) void k_gemm(const float* __restrict__ X,
                                              const float* __restrict__ W,
                                              int M) {
    extern __shared__ float smem[];
    float* As = smem;                       // [64][130]
    float* Bs = smem + BM * ASTRIDE;        // [128][128]

    int tid = threadIdx.x;
    int m0  = blockIdx.x * BM;
    int tmr = (tid >> 4) * TM;       // 0,8,...,56
    int tnc = (tid & 15) * 4;        // 0,4,...,60

    // Load A tile: 64x128 floats = 2048 float4, 16/thread, coalesced,
    // scalar STS (stride 130 breaks 16B alignment for vector stores).
#pragma unroll
    for (int j = 0; j < 16; j++) {
        int idx = tid + j * 128;
        int r   = idx >> 5;
        int c4  = idx & 31;
        float4 v = make_float4(0.f, 0.f, 0.f, 0.f);
        int gr = m0 + r;
        if (gr < M)
            v = *(const float4*)(X + (size_t)gr * NFEAT + c4 * 4);
        float* ap = As + r * ASTRIDE + c4 * 4;
        ap[0] = v.x; ap[1] = v.y; ap[2] = v.z; ap[3] = v.w;
    }
    // Load B (all of W): 128x128 floats = 4096 float4, 32/thread.
#pragma unroll
    for (int j = 0; j < 32; j++) {
        int idx = tid + j * 128;
        int r   = idx >> 5;
        int c4  = idx & 31;
        *(float4*)(Bs + r * NFEAT + c4 * 4) =
            *(const float4*)(W + (size_t)r * NFEAT + c4 * 4);
    }
    __syncthreads();

    unsigned long long acc[TM][4];
#pragma unroll
    for (int i = 0; i < TM; i++)
#pragma unroll
        for (int j = 0; j < 4; j++) acc[i][j] = 0ULL;

#pragma unroll 8
    for (int k = 0; k < NFEAT; k++) {
        unsigned long long apair[TM];
#pragma unroll
        for (int i = 0; i < TM; i++) {
            float a = As[(tmr + i) * ASTRIDE + k];
            asm("mov.b64 %0, {%1,%1};" : "=l"(apair[i]) : "f"(a));
        }
        float4 b0 = *(const float4*)(Bs + k * NFEAT + tnc);
        float4 b1 = *(const float4*)(Bs + k * NFEAT + 64 + tnc);
        unsigned long long bpair[4];
        asm("mov.b64 %0, {%1,%2};" : "=l"(bpair[0]) : "f"(b0.x), "f"(b0.y));
        asm("mov.b64 %0, {%1,%2};" : "=l"(bpair[1]) : "f"(b0.z), "f"(b0.w));
        asm("mov.b64 %0, {%1,%2};" : "=l"(bpair[2]) : "f"(b1.x), "f"(b1.y));
        asm("mov.b64 %0, {%1,%2};" : "=l"(bpair[3]) : "f"(b1.z), "f"(b1.w));

#pragma unroll
        for (int i = 0; i < TM; i++)
#pragma unroll
            for (int j = 0; j < 4; j++)
                asm("fma.rn.f32x2 %0, %1, %2, %0;"
                    : "+l"(acc[i][j])
                    : "l"(apair[i]), "l"(bpair[j]));
    }

#pragma unroll
    for (int i = 0; i < TM; i++) {
        int gr = m0 + tmr + i;
        if (gr < M) {
            float dv = g_dinv[gr];
            float o[8];
#pragma unroll
            for (int j = 0; j < 4; j++)
                asm("mov.b64 {%0,%1}, %2;" : "=f"(o[2 * j]), "=f"(o[2 * j + 1])
                    : "l"(acc[i][j]));
            __half2 p0 = __floats2half2_rn(o[0] * dv, o[1] * dv);
            __half2 p1 = __floats2half2_rn(o[2] * dv, o[3] * dv);
            __half2 p2 = __floats2half2_rn(o[4] * dv, o[5] * dv);
            __half2 p3 = __floats2half2_rn(o[6] * dv, o[7] * dv);
            __half2* rowp = g_hh + (size_t)gr * (NFEAT / 2);
            uint2 u0, u1;
            u0.x = *(unsigned*)&p0; u0.y = *(unsigned*)&p1;
            u1.x = *(unsigned*)&p2; u1.y = *(unsigned*)&p3;
            *(uint2*)(rowp + (tnc >> 1))        = u0;  // cols tnc..tnc+3
            *(uint2*)(rowp + ((64 + tnc) >> 1)) = u1;  // cols 64+tnc..
        }
    }
}

#define GEMM_SMEM ((BM * ASTRIDE + NFEAT * NFEAT) * (int)sizeof(float))

// ---------------------------------------------------------------------------
// Warp-shuffle scans
__global__ void k_scan1(int n) {
    __shared__ int ws[8];
    int t = threadIdx.x, lane = t & 31, wid = t >> 5;
    int i = blockIdx.x * 256 + t;
    int x = (i < n) ? g_cnt[i] : 0;
#pragma unroll
    for (int ofs = 1; ofs < 32; ofs <<= 1) {
        int y = __shfl_up_sync(0xffffffffu, x, ofs);
        if (lane >= ofs) x += y;
    }
    if (lane == 31) ws[wid] = x;
    __syncthreads();
    if (wid == 0) {
        int y = (lane < 8) ? ws[lane] : 0;
#pragma unroll
        for (int ofs = 1; ofs < 8; ofs <<= 1) {
            int z = __shfl_up_sync(0xffffffffu, y, ofs);
            if (lane >= ofs) y += z;
        }
        if (lane < 8) ws[lane] = y;
    }
    __syncthreads();
    int incl = x + (wid > 0 ? ws[wid - 1] : 0);
    if (i < n) g_scan[i] = incl;
    if (t == 255) g_part[blockIdx.x] = incl;
}

__global__ void k_scan2(int nb) {
    __shared__ int ws[16];
    int t = threadIdx.x, lane = t & 31, wid = t >> 5;
    int x = (t < nb) ? g_part[t] : 0;
#pragma unroll
    for (int ofs = 1; ofs < 32; ofs <<= 1) {
        int y = __shfl_up_sync(0xffffffffu, x, ofs);
        if (lane >= ofs) x += y;
    }
    if (lane == 31) ws[wid] = x;
    __syncthreads();
    if (wid == 0) {
        int y = (lane < 16) ? ws[lane] : 0;
#pragma unroll
        for (int ofs = 1; ofs < 16; ofs <<= 1) {
            int z = __shfl_up_sync(0xffffffffu, y, ofs);
            if (lane >= ofs) y += z;
        }
        if (lane < 16) ws[lane] = y;
    }
    __syncthreads();
    int incl = x + (wid > 0 ? ws[wid - 1] : 0);
    if (t < nb) g_part[t] = incl;
}

__global__ void k_scan3(int n) {
    int i = blockIdx.x * blockDim.x + threadIdx.x;
    if (i >= n) return;
    int b = i >> 8;
    int off = g_scan[i] - g_cnt[i] + (b > 0 ? g_part[b - 1] : 0);
    g_off[i] = off;
    g_cursor[i] = off;
}

__global__ void k_csr4(const int* __restrict__ ei, int E) {
    int e4 = blockIdx.x * blockDim.x + threadIdx.x;
    if (e4 * 4 >= E) return;
    int4 s = ((const int4*)ei)[e4];
    int4 d = ((const int4*)(ei + E))[e4];
    g_csr[atomicAdd(&g_cursor[d.x], 1)] = s.x;
    g_csr[atomicAdd(&g_cursor[d.y], 1)] = s.y;
    g_csr[atomicAdd(&g_cursor[d.z], 1)] = s.z;
    g_csr[atomicAdd(&g_cursor[d.w], 1)] = s.w;
}
__global__ void k_csr1(const int* __restrict__ ei, int E) {
    int e = blockIdx.x * blockDim.x + threadIdx.x;
    if (e >= E) return;
    g_csr[atomicAdd(&g_cursor[ei[E + e]], 1)] = ei[e];
}

// ---------------------------------------------------------------------------
// Gather: one warp per dst node, fp16 rows (256 B), fp32 accumulation.
__global__ __launch_bounds__(256) void k_gather(const float* __restrict__ b,
                                                float* __restrict__ out, int N) {
    int node = blockIdx.x * 8 + (threadIdx.x >> 5);
    if (node >= N) return;
    int lane = threadIdx.x & 31;

    int base = g_off[node];
    int cnt  = g_cnt[node];
    float dd = g_dinv[node];

    float4 acc;
    {
        uint2 u = ((const uint2*)(g_hh + (size_t)node * (NFEAT / 2)))[lane];
        float2 f0 = __half22float2(*(__half2*)&u.x);
        float2 f1 = __half22float2(*(__half2*)&u.y);
        acc = make_float4(f0.x, f0.y, f1.x, f1.y);
    }

    int i = 0;
    for (; i + 4 <= cnt; i += 4) {
        int s0 = g_csr[base + i];
        int s1 = g_csr[base + i + 1];
        int s2 = g_csr[base + i + 2];
        int s3 = g_csr[base + i + 3];
        uint2 u0 = ((const uint2*)(g_hh + (size_t)s0 * (NFEAT / 2)))[lane];
        uint2 u1 = ((const uint2*)(g_hh + (size_t)s1 * (NFEAT / 2)))[lane];
        uint2 u2 = ((const uint2*)(g_hh + (size_t)s2 * (NFEAT / 2)))[lane];
        uint2 u3 = ((const uint2*)(g_hh + (size_t)s3 * (NFEAT / 2)))[lane];
        float2 a0 = __half22float2(*(__half2*)&u0.x), a1 = __half22float2(*(__half2*)&u0.y);
        float2 c0 = __half22float2(*(__half2*)&u1.x), c1 = __half22float2(*(__half2*)&u1.y);
        float2 d0 = __half22float2(*(__half2*)&u2.x), d1 = __half22float2(*(__half2*)&u2.y);
        float2 e0 = __half22float2(*(__half2*)&u3.x), e1 = __half22float2(*(__half2*)&u3.y);
        acc.x += a0.x + c0.x + d0.x + e0.x;
        acc.y += a0.y + c0.y + d0.y + e0.y;
        acc.z += a1.x + c1.x + d1.x + e1.x;
        acc.w += a1.y + c1.y + d1.y + e1.y;
    }
    for (; i < cnt; i++) {
        int s0 = g_csr[base + i];
        uint2 u0 = ((const uint2*)(g_hh + (size_t)s0 * (NFEAT / 2)))[lane];
        float2 a0 = __half22float2(*(__half2*)&u0.x), a1 = __half22float2(*(__half2*)&u0.y);
        acc.x += a0.x; acc.y += a0.y; acc.z += a1.x; acc.w += a1.y;
    }

    float4 bv = ((const float4*)b)[lane];
    float4 o;
    o.x = bv.x + acc.x * dd;
    o.y = bv.y + acc.y * dd;
    o.z = bv.z + acc.z * dd;
    o.w = bv.w + acc.w * dd;
    ((float4*)(out + (size_t)node * NFEAT))[lane] = o;
}

// ---------------------------------------------------------------------------
extern "C" void kernel_launch(void* const* d_in, const int* in_sizes, int n_in,
                              void* d_out, int out_size) {
    const float* x  = (const float*)d_in[0];
    const int*   ei = (const int*)d_in[1];
    const float* w  = (const float*)d_in[2];
    const float* b  = (const float*)d_in[3];
    float* out = (float*)d_out;

    int N = in_sizes[0] / NFEAT;
    int E = in_sizes[1] / 2;
    int NB = (N + 255) / 256;

    cudaFuncSetAttribute(k_gemm, cudaFuncAttributeMaxDynamicSharedMemorySize,
                         GEMM_SMEM);

    k_zero_cnt<<<(N + 255) / 256, 256>>>(N);
    if ((E & 3) == 0)
        k_count4<<<(E / 4 + 255) / 256, 256>>>(ei, E);
    else
        k_count1<<<(E + 255) / 256, 256>>>(ei, E);
    k_dinv<<<(N + 255) / 256, 256>>>(N);
    k_gemm<<<(N + BM - 1) / BM, 128, GEMM_SMEM>>>(x, w, N);  // idx 3 -> profiled
    k_scan1<<<NB, 256>>>(N);
    k_scan2<<<1, 512>>>(NB);
    k_scan3<<<(N + 255) / 256, 256>>>(N);
    if ((E & 3) == 0)
        k_csr4<<<(E / 4 + 255) / 256, 256>>>(ei, E);
    else
        k_csr1<<<(E + 255) / 256, 256>>>(ei, E);
    k_gather<<<(N + 7) / 8, 256>>>(b, out, N);
}

// round 11
// speedup vs baseline: 1.3443x; 1.3443x over previous
#include <cuda_runtime.h>
#include <cuda_fp16.h>
#include <cstdint>

#define NNODES_MAX 100000
#define NEDGES_MAX 2000000
#define NFEAT 128

// Scratch (allocation-free rule: __device__ globals)
__device__ __half2 g_hh[(size_t)NNODES_MAX * (NFEAT / 2)];  // h' = (x@W)*dinv, fp16
__device__ float g_dinv[NNODES_MAX];
__device__ int   g_cnt[NNODES_MAX];
__device__ int   g_scan[NNODES_MAX];
__device__ int   g_part[512];
__device__ int   g_off[NNODES_MAX];
__device__ int   g_cursor[NNODES_MAX];
__device__ int   g_csr[NEDGES_MAX];

// ---------------------------------------------------------------------------
__global__ void k_zero_cnt(int n) {
    int i = blockIdx.x * blockDim.x + threadIdx.x;
    if (i < n) g_cnt[i] = 0;
}

__global__ void k_count4(const int* __restrict__ ei, int E) {
    int e4 = blockIdx.x * blockDim.x + threadIdx.x;
    if (e4 * 4 >= E) return;
    int4 d = ((const int4*)(ei + E))[e4];
    atomicAdd(&g_cnt[d.x], 1);
    atomicAdd(&g_cnt[d.y], 1);
    atomicAdd(&g_cnt[d.z], 1);
    atomicAdd(&g_cnt[d.w], 1);
}
__global__ void k_count1(const int* __restrict__ ei, int E) {
    int e = blockIdx.x * blockDim.x + threadIdx.x;
    if (e < E) atomicAdd(&g_cnt[ei[E + e]], 1);
}

__global__ void k_dinv(int n) {
    int i = blockIdx.x * blockDim.x + threadIdx.x;
    if (i < n) g_dinv[i] = rsqrtf((float)g_cnt[i] + 1.0f);
}

// ---------------------------------------------------------------------------
// Tensor-core GEMM: h' = (x @ W) * dinv, fp16 inputs / fp32 accumulate.
// BM=128 rows/block, 256 threads (8 warps), warp owns 16 rows x ALL 128 cols.
// smem: Xs[128][136] fp16, Wh[128][136] fp16  (stride 136 -> LDSM conflict-free)
#define XS_STRIDE 136
#define GEMM_SMEM (2 * 128 * XS_STRIDE * (int)sizeof(__half))

__global__ __launch_bounds__(256) void k_gemm(const float* __restrict__ X,
                                              const float* __restrict__ W,
                                              int M) {
    extern __shared__ __half smem[];
    __half* Xs = smem;                       // [128][136]
    __half* Wh = smem + 128 * XS_STRIDE;     // [128][136]

    int tid = threadIdx.x;
    int m0  = blockIdx.x * 128;

    // Load + convert X tile (128x128 f32 -> fp16): 4096 float4, 16/thread
#pragma unroll
    for (int j = 0; j < 16; j++) {
        int idx = tid + j * 256;        // 0..4095
        int r   = idx >> 5;             // 0..127
        int c4  = idx & 31;             // 0..31
        float4 v = make_float4(0.f, 0.f, 0.f, 0.f);
        int gr = m0 + r;
        if (gr < M)
            v = *(const float4*)(X + (size_t)gr * NFEAT + c4 * 4);
        __half2 h0 = __floats2half2_rn(v.x, v.y);
        __half2 h1 = __floats2half2_rn(v.z, v.w);
        uint2 u; u.x = *(unsigned*)&h0; u.y = *(unsigned*)&h1;
        *(uint2*)(Xs + r * XS_STRIDE + c4 * 4) = u;
    }
    // Load + convert W (128x128): same pattern
#pragma unroll
    for (int j = 0; j < 16; j++) {
        int idx = tid + j * 256;
        int r   = idx >> 5;
        int c4  = idx & 31;
        float4 v = *(const float4*)(W + (size_t)r * NFEAT + c4 * 4);
        __half2 h0 = __floats2half2_rn(v.x, v.y);
        __half2 h1 = __floats2half2_rn(v.z, v.w);
        uint2 u; u.x = *(unsigned*)&h0; u.y = *(unsigned*)&h1;
        *(uint2*)(Wh + r * XS_STRIDE + c4 * 4) = u;
    }
    __syncthreads();

    int lane = tid & 31;
    int wrp  = tid >> 5;        // 0..7
    int mrow = wrp * 16;

    float acc[16][4];            // 16 n-tiles of 8 cols = full 128 cols
#pragma unroll
    for (int i = 0; i < 16; i++)
#pragma unroll
        for (int j = 0; j < 4; j++) acc[i][j] = 0.f;

    unsigned xs_base = (unsigned)__cvta_generic_to_shared(Xs);
    unsigned wh_base = (unsigned)__cvta_generic_to_shared(Wh);

#pragma unroll
    for (int kt = 0; kt < 8; kt++) {
        int k0 = kt * 16;
        // A fragment 16x16: lanes 0-15 -> rows mrow+(lane&15), col k0;
        //                   lanes 16-31 -> same rows, col k0+8
        unsigned a_addr = xs_base +
            (((mrow + (lane & 15)) * XS_STRIDE + k0 + (lane >> 4) * 8) << 1);
        unsigned a0, a1, a2, a3;
        asm volatile("ldmatrix.sync.aligned.m8n8.x4.shared.b16 {%0,%1,%2,%3}, [%4];"
                     : "=r"(a0), "=r"(a1), "=r"(a2), "=r"(a3) : "r"(a_addr));

#pragma unroll
        for (int nt2 = 0; nt2 < 8; nt2++) {
            int n0 = nt2 * 16;
            // B fragments (2 n-tiles): trans load of Wh[k0+(lane&15)][n0 + (lane>>4)*8]
            unsigned b_addr = wh_base +
                (((k0 + (lane & 15)) * XS_STRIDE + n0 + (lane >> 4) * 8) << 1);
            unsigned b0, b1, b2, b3;
            asm volatile("ldmatrix.sync.aligned.m8n8.x4.trans.shared.b16 {%0,%1,%2,%3}, [%4];"
                         : "=r"(b0), "=r"(b1), "=r"(b2), "=r"(b3) : "r"(b_addr));

            asm volatile("mma.sync.aligned.m16n8k16.row.col.f32.f16.f16.f32 "
                         "{%0,%1,%2,%3}, {%4,%5,%6,%7}, {%8,%9}, {%0,%1,%2,%3};"
                         : "+f"(acc[2 * nt2][0]), "+f"(acc[2 * nt2][1]),
                           "+f"(acc[2 * nt2][2]), "+f"(acc[2 * nt2][3])
                         : "r"(a0), "r"(a1), "r"(a2), "r"(a3), "r"(b0), "r"(b1));
            asm volatile("mma.sync.aligned.m16n8k16.row.col.f32.f16.f16.f32 "
                         "{%0,%1,%2,%3}, {%4,%5,%6,%7}, {%8,%9}, {%0,%1,%2,%3};"
                         : "+f"(acc[2 * nt2 + 1][0]), "+f"(acc[2 * nt2 + 1][1]),
                           "+f"(acc[2 * nt2 + 1][2]), "+f"(acc[2 * nt2 + 1][3])
                         : "r"(a0), "r"(a1), "r"(a2), "r"(a3), "r"(b2), "r"(b3));
        }
    }

    // Epilogue: scale by dinv, pack fp16.
    // Lane (g = lane>>2, t = lane&3) owns rows (mrow+g, mrow+g+8),
    // cols 8*nt + 2t, 2t+1 per n-tile (nt = 0..15 -> cols 0..127).
    int g = lane >> 2, t = lane & 3;
    int r0 = m0 + mrow + g;
    int r1 = r0 + 8;
    float dv0 = (r0 < M) ? g_dinv[r0] : 0.f;
    float dv1 = (r1 < M) ? g_dinv[r1] : 0.f;
#pragma unroll
    for (int nt = 0; nt < 16; nt++) {
        if (r0 < M)
            g_hh[(size_t)r0 * (NFEAT / 2) + nt * 4 + t] =
                __floats2half2_rn(acc[nt][0] * dv0, acc[nt][1] * dv0);
        if (r1 < M)
            g_hh[(size_t)r1 * (NFEAT / 2) + nt * 4 + t] =
                __floats2half2_rn(acc[nt][2] * dv1, acc[nt][3] * dv1);
    }
}

// ---------------------------------------------------------------------------
// Warp-shuffle scans
__global__ void k_scan1(int n) {
    __shared__ int ws[8];
    int t = threadIdx.x, lane = t & 31, wid = t >> 5;
    int i = blockIdx.x * 256 + t;
    int x = (i < n) ? g_cnt[i] : 0;
#pragma unroll
    for (int ofs = 1; ofs < 32; ofs <<= 1) {
        int y = __shfl_up_sync(0xffffffffu, x, ofs);
        if (lane >= ofs) x += y;
    }
    if (lane == 31) ws[wid] = x;
    __syncthreads();
    if (wid == 0) {
        int y = (lane < 8) ? ws[lane] : 0;
#pragma unroll
        for (int ofs = 1; ofs < 8; ofs <<= 1) {
            int z = __shfl_up_sync(0xffffffffu, y, ofs);
            if (lane >= ofs) y += z;
        }
        if (lane < 8) ws[lane] = y;
    }
    __syncthreads();
    int incl = x + (wid > 0 ? ws[wid - 1] : 0);
    if (i < n) g_scan[i] = incl;
    if (t == 255) g_part[blockIdx.x] = incl;
}

__global__ void k_scan2(int nb) {
    __shared__ int ws[16];
    int t = threadIdx.x, lane = t & 31, wid = t >> 5;
    int x = (t < nb) ? g_part[t] : 0;
#pragma unroll
    for (int ofs = 1; ofs < 32; ofs <<= 1) {
        int y = __shfl_up_sync(0xffffffffu, x, ofs);
        if (lane >= ofs) x += y;
    }
    if (lane == 31) ws[wid] = x;
    __syncthreads();
    if (wid == 0) {
        int y = (lane < 16) ? ws[lane] : 0;
#pragma unroll
        for (int ofs = 1; ofs < 16; ofs <<= 1) {
            int z = __shfl_up_sync(0xffffffffu, y, ofs);
            if (lane >= ofs) y += z;
        }
        if (lane < 16) ws[lane] = y;
    }
    __syncthreads();
    int incl = x + (wid > 0 ? ws[wid - 1] : 0);
    if (t < nb) g_part[t] = incl;
}

__global__ void k_scan3(int n) {
    int i = blockIdx.x * blockDim.x + threadIdx.x;
    if (i >= n) return;
    int b = i >> 8;
    int off = g_scan[i] - g_cnt[i] + (b > 0 ? g_part[b - 1] : 0);
    g_off[i] = off;
    g_cursor[i] = off;
}

__global__ void k_csr4(const int* __restrict__ ei, int E) {
    int e4 = blockIdx.x * blockDim.x + threadIdx.x;
    if (e4 * 4 >= E) return;
    int4 s = ((const int4*)ei)[e4];
    int4 d = ((const int4*)(ei + E))[e4];
    g_csr[atomicAdd(&g_cursor[d.x], 1)] = s.x;
    g_csr[atomicAdd(&g_cursor[d.y], 1)] = s.y;
    g_csr[atomicAdd(&g_cursor[d.z], 1)] = s.z;
    g_csr[atomicAdd(&g_cursor[d.w], 1)] = s.w;
}
__global__ void k_csr1(const int* __restrict__ ei, int E) {
    int e = blockIdx.x * blockDim.x + threadIdx.x;
    if (e >= E) return;
    g_csr[atomicAdd(&g_cursor[ei[E + e]], 1)] = ei[e];
}

// ---------------------------------------------------------------------------
// Gather: one warp per dst node, fp16 rows (256 B), fp32 accumulation.
__global__ __launch_bounds__(256) void k_gather(const float* __restrict__ b,
                                                float* __restrict__ out, int N) {
    int node = blockIdx.x * 8 + (threadIdx.x >> 5);
    if (node >= N) return;
    int lane = threadIdx.x & 31;

    int base = g_off[node];
    int cnt  = g_cnt[node];
    float dd = g_dinv[node];

    float4 acc;
    {
        uint2 u = ((const uint2*)(g_hh + (size_t)node * (NFEAT / 2)))[lane];
        float2 f0 = __half22float2(*(__half2*)&u.x);
        float2 f1 = __half22float2(*(__half2*)&u.y);
        acc = make_float4(f0.x, f0.y, f1.x, f1.y);
    }

    int i = 0;
    for (; i + 4 <= cnt; i += 4) {
        int s0 = g_csr[base + i];
        int s1 = g_csr[base + i + 1];
        int s2 = g_csr[base + i + 2];
        int s3 = g_csr[base + i + 3];
        uint2 u0 = ((const uint2*)(g_hh + (size_t)s0 * (NFEAT / 2)))[lane];
        uint2 u1 = ((const uint2*)(g_hh + (size_t)s1 * (NFEAT / 2)))[lane];
        uint2 u2 = ((const uint2*)(g_hh + (size_t)s2 * (NFEAT / 2)))[lane];
        uint2 u3 = ((const uint2*)(g_hh + (size_t)s3 * (NFEAT / 2)))[lane];
        float2 a0 = __half22float2(*(__half2*)&u0.x), a1 = __half22float2(*(__half2*)&u0.y);
        float2 c0 = __half22float2(*(__half2*)&u1.x), c1 = __half22float2(*(__half2*)&u1.y);
        float2 d0 = __half22float2(*(__half2*)&u2.x), d1 = __half22float2(*(__half2*)&u2.y);
        float2 e0 = __half22float2(*(__half2*)&u3.x), e1 = __half22float2(*(__half2*)&u3.y);
        acc.x += a0.x + c0.x + d0.x + e0.x;
        acc.y += a0.y + c0.y + d0.y + e0.y;
        acc.z += a1.x + c1.x + d1.x + e1.x;
        acc.w += a1.y + c1.y + d1.y + e1.y;
    }
    for (; i < cnt; i++) {
        int s0 = g_csr[base + i];
        uint2 u0 = ((const uint2*)(g_hh + (size_t)s0 * (NFEAT / 2)))[lane];
        float2 a0 = __half22float2(*(__half2*)&u0.x), a1 = __half22float2(*(__half2*)&u0.y);
        acc.x += a0.x; acc.y += a0.y; acc.z += a1.x; acc.w += a1.y;
    }

    float4 bv = ((const float4*)b)[lane];
    float4 o;
    o.x = bv.x + acc.x * dd;
    o.y = bv.y + acc.y * dd;
    o.z = bv.z + acc.z * dd;
    o.w = bv.w + acc.w * dd;
    ((float4*)(out + (size_t)node * NFEAT))[lane] = o;
}

// ---------------------------------------------------------------------------
extern "C" void kernel_launch(void* const* d_in, const int* in_sizes, int n_in,
                              void* d_out, int out_size) {
    const float* x  = (const float*)d_in[0];
    const int*   ei = (const int*)d_in[1];
    const float* w  = (const float*)d_in[2];
    const float* b  = (const float*)d_in[3];
    float* out = (float*)d_out;

    int N = in_sizes[0] / NFEAT;
    int E = in_sizes[1] / 2;
    int NB = (N + 255) / 256;

    cudaFuncSetAttribute(k_gemm, cudaFuncAttributeMaxDynamicSharedMemorySize,
                         GEMM_SMEM);

    k_zero_cnt<<<(N + 255) / 256, 256>>>(N);
    if ((E & 3) == 0)
        k_count4<<<(E / 4 + 255) / 256, 256>>>(ei, E);
    else
        k_count1<<<(E + 255) / 256, 256>>>(ei, E);
    k_dinv<<<(N + 255) / 256, 256>>>(N);
    k_gemm<<<(N + 127) / 128, 256, GEMM_SMEM>>>(x, w, N);  // idx 3 -> profiled
    k_scan1<<<NB, 256>>>(N);
    k_scan2<<<1, 512>>>(NB);
    k_scan3<<<(N + 255) / 256, 256>>>(N);
    if ((E & 3) == 0)
        k_csr4<<<(E / 4 + 255) / 256, 256>>>(ei, E);
    else
        k_csr1<<<(E + 255) / 256, 256>>>(ei, E);
    k_gather<<<(N + 7) / 8, 256>>>(b, out, N);
}

// round 12
// speedup vs baseline: 1.3575x; 1.0098x over previous
#include <cuda_runtime.h>
#include <cuda_fp16.h>
#include <cstdint>

#define NNODES_MAX 100000
#define NEDGES_MAX 2000000
#define NFEAT 128

// Scratch (allocation-free rule: __device__ globals)
__device__ __half2 g_hh[(size_t)NNODES_MAX * (NFEAT / 2)];  // h = x@W (UNscaled), fp16
__device__ float g_dinv[NNODES_MAX];
__device__ int   g_cnt[NNODES_MAX];
__device__ int   g_scan[NNODES_MAX];
__device__ int   g_part[512];
__device__ int   g_off[NNODES_MAX];
__device__ int   g_cursor[NNODES_MAX];
__device__ int   g_csr[NEDGES_MAX];

// Static stream/event for graph fork-join (created once at load; no device mem)
static cudaStream_t g_s2;
static cudaEvent_t  g_ev_fork, g_ev_join;
static struct GInit {
    GInit() {
        cudaStreamCreate(&g_s2);
        cudaEventCreateWithFlags(&g_ev_fork, cudaEventDisableTiming);
        cudaEventCreateWithFlags(&g_ev_join, cudaEventDisableTiming);
    }
} g_ginit;

// ---------------------------------------------------------------------------
__global__ void k_zero_cnt(int n) {
    int i = blockIdx.x * blockDim.x + threadIdx.x;
    if (i < n) g_cnt[i] = 0;
}

__global__ void k_count4(const int* __restrict__ ei, int E) {
    int e4 = blockIdx.x * blockDim.x + threadIdx.x;
    if (e4 * 4 >= E) return;
    int4 d = ((const int4*)(ei + E))[e4];
    atomicAdd(&g_cnt[d.x], 1);
    atomicAdd(&g_cnt[d.y], 1);
    atomicAdd(&g_cnt[d.z], 1);
    atomicAdd(&g_cnt[d.w], 1);
}
__global__ void k_count1(const int* __restrict__ ei, int E) {
    int e = blockIdx.x * blockDim.x + threadIdx.x;
    if (e < E) atomicAdd(&g_cnt[ei[E + e]], 1);
}

// ---------------------------------------------------------------------------
// Tensor-core GEMM: h = x @ W (no dinv — independent of graph stats).
#define XS_STRIDE 136
#define GEMM_SMEM (2 * 128 * XS_STRIDE * (int)sizeof(__half))

__global__ __launch_bounds__(256) void k_gemm(const float* __restrict__ X,
                                              const float* __restrict__ W,
                                              int M) {
    extern __shared__ __half smem[];
    __half* Xs = smem;                       // [128][136]
    __half* Wh = smem + 128 * XS_STRIDE;     // [128][136]

    int tid = threadIdx.x;
    int m0  = blockIdx.x * 128;

#pragma unroll
    for (int j = 0; j < 16; j++) {
        int idx = tid + j * 256;
        int r   = idx >> 5;
        int c4  = idx & 31;
        float4 v = make_float4(0.f, 0.f, 0.f, 0.f);
        int gr = m0 + r;
        if (gr < M)
            v = *(const float4*)(X + (size_t)gr * NFEAT + c4 * 4);
        __half2 h0 = __floats2half2_rn(v.x, v.y);
        __half2 h1 = __floats2half2_rn(v.z, v.w);
        uint2 u; u.x = *(unsigned*)&h0; u.y = *(unsigned*)&h1;
        *(uint2*)(Xs + r * XS_STRIDE + c4 * 4) = u;
    }
#pragma unroll
    for (int j = 0; j < 16; j++) {
        int idx = tid + j * 256;
        int r   = idx >> 5;
        int c4  = idx & 31;
        float4 v = *(const float4*)(W + (size_t)r * NFEAT + c4 * 4);
        __half2 h0 = __floats2half2_rn(v.x, v.y);
        __half2 h1 = __floats2half2_rn(v.z, v.w);
        uint2 u; u.x = *(unsigned*)&h0; u.y = *(unsigned*)&h1;
        *(uint2*)(Wh + r * XS_STRIDE + c4 * 4) = u;
    }
    __syncthreads();

    int lane = tid & 31;
    int wrp  = tid >> 5;
    int mrow = wrp * 16;

    float acc[16][4];
#pragma unroll
    for (int i = 0; i < 16; i++)
#pragma unroll
        for (int j = 0; j < 4; j++) acc[i][j] = 0.f;

    unsigned xs_base = (unsigned)__cvta_generic_to_shared(Xs);
    unsigned wh_base = (unsigned)__cvta_generic_to_shared(Wh);

#pragma unroll
    for (int kt = 0; kt < 8; kt++) {
        int k0 = kt * 16;
        unsigned a_addr = xs_base +
            (((mrow + (lane & 15)) * XS_STRIDE + k0 + (lane >> 4) * 8) << 1);
        unsigned a0, a1, a2, a3;
        asm volatile("ldmatrix.sync.aligned.m8n8.x4.shared.b16 {%0,%1,%2,%3}, [%4];"
                     : "=r"(a0), "=r"(a1), "=r"(a2), "=r"(a3) : "r"(a_addr));

#pragma unroll
        for (int nt2 = 0; nt2 < 8; nt2++) {
            int n0 = nt2 * 16;
            unsigned b_addr = wh_base +
                (((k0 + (lane & 15)) * XS_STRIDE + n0 + (lane >> 4) * 8) << 1);
            unsigned b0, b1, b2, b3;
            asm volatile("ldmatrix.sync.aligned.m8n8.x4.trans.shared.b16 {%0,%1,%2,%3}, [%4];"
                         : "=r"(b0), "=r"(b1), "=r"(b2), "=r"(b3) : "r"(b_addr));

            asm volatile("mma.sync.aligned.m16n8k16.row.col.f32.f16.f16.f32 "
                         "{%0,%1,%2,%3}, {%4,%5,%6,%7}, {%8,%9}, {%0,%1,%2,%3};"
                         : "+f"(acc[2 * nt2][0]), "+f"(acc[2 * nt2][1]),
                           "+f"(acc[2 * nt2][2]), "+f"(acc[2 * nt2][3])
                         : "r"(a0), "r"(a1), "r"(a2), "r"(a3), "r"(b0), "r"(b1));
            asm volatile("mma.sync.aligned.m16n8k16.row.col.f32.f16.f16.f32 "
                         "{%0,%1,%2,%3}, {%4,%5,%6,%7}, {%8,%9}, {%0,%1,%2,%3};"
                         : "+f"(acc[2 * nt2 + 1][0]), "+f"(acc[2 * nt2 + 1][1]),
                           "+f"(acc[2 * nt2 + 1][2]), "+f"(acc[2 * nt2 + 1][3])
                         : "r"(a0), "r"(a1), "r"(a2), "r"(a3), "r"(b2), "r"(b3));
        }
    }

    int g = lane >> 2, t = lane & 3;
    int r0 = m0 + mrow + g;
    int r1 = r0 + 8;
#pragma unroll
    for (int nt = 0; nt < 16; nt++) {
        if (r0 < M)
            g_hh[(size_t)r0 * (NFEAT / 2) + nt * 4 + t] =
                __floats2half2_rn(acc[nt][0], acc[nt][1]);
        if (r1 < M)
            g_hh[(size_t)r1 * (NFEAT / 2) + nt * 4 + t] =
                __floats2half2_rn(acc[nt][2], acc[nt][3]);
    }
}

// ---------------------------------------------------------------------------
// Warp-shuffle scans
__global__ void k_scan1(int n) {
    __shared__ int ws[8];
    int t = threadIdx.x, lane = t & 31, wid = t >> 5;
    int i = blockIdx.x * 256 + t;
    int x = (i < n) ? g_cnt[i] : 0;
#pragma unroll
    for (int ofs = 1; ofs < 32; ofs <<= 1) {
        int y = __shfl_up_sync(0xffffffffu, x, ofs);
        if (lane >= ofs) x += y;
    }
    if (lane == 31) ws[wid] = x;
    __syncthreads();
    if (wid == 0) {
        int y = (lane < 8) ? ws[lane] : 0;
#pragma unroll
        for (int ofs = 1; ofs < 8; ofs <<= 1) {
            int z = __shfl_up_sync(0xffffffffu, y, ofs);
            if (lane >= ofs) y += z;
        }
        if (lane < 8) ws[lane] = y;
    }
    __syncthreads();
    int incl = x + (wid > 0 ? ws[wid - 1] : 0);
    if (i < n) g_scan[i] = incl;
    if (t == 255) g_part[blockIdx.x] = incl;
}

__global__ void k_scan2(int nb) {
    __shared__ int ws[16];
    int t = threadIdx.x, lane = t & 31, wid = t >> 5;
    int x = (t < nb) ? g_part[t] : 0;
#pragma unroll
    for (int ofs = 1; ofs < 32; ofs <<= 1) {
        int y = __shfl_up_sync(0xffffffffu, x, ofs);
        if (lane >= ofs) x += y;
    }
    if (lane == 31) ws[wid] = x;
    __syncthreads();
    if (wid == 0) {
        int y = (lane < 16) ? ws[lane] : 0;
#pragma unroll
        for (int ofs = 1; ofs < 16; ofs <<= 1) {
            int z = __shfl_up_sync(0xffffffffu, y, ofs);
            if (lane >= ofs) y += z;
        }
        if (lane < 16) ws[lane] = y;
    }
    __syncthreads();
    int incl = x + (wid > 0 ? ws[wid - 1] : 0);
    if (t < nb) g_part[t] = incl;
}

// scan3 + dinv fused (both read g_cnt)
__global__ void k_scan3(int n) {
    int i = blockIdx.x * blockDim.x + threadIdx.x;
    if (i >= n) return;
    int b = i >> 8;
    int c = g_cnt[i];
    int off = g_scan[i] - c + (b > 0 ? g_part[b - 1] : 0);
    g_off[i] = off;
    g_cursor[i] = off;
    g_dinv[i] = rsqrtf((float)c + 1.0f);
}

__global__ void k_csr4(const int* __restrict__ ei, int E) {
    int e4 = blockIdx.x * blockDim.x + threadIdx.x;
    if (e4 * 4 >= E) return;
    int4 s = ((const int4*)ei)[e4];
    int4 d = ((const int4*)(ei + E))[e4];
    g_csr[atomicAdd(&g_cursor[d.x], 1)] = s.x;
    g_csr[atomicAdd(&g_cursor[d.y], 1)] = s.y;
    g_csr[atomicAdd(&g_cursor[d.z], 1)] = s.z;
    g_csr[atomicAdd(&g_cursor[d.w], 1)] = s.w;
}
__global__ void k_csr1(const int* __restrict__ ei, int E) {
    int e = blockIdx.x * blockDim.x + threadIdx.x;
    if (e >= E) return;
    g_csr[atomicAdd(&g_cursor[ei[E + e]], 1)] = ei[e];
}

// ---------------------------------------------------------------------------
// Gather: one warp per dst node; h unscaled -> apply dinv[src] per edge.
// out = (sum_src dinv[s]*h[s] + dinv[node]*h[node]) * dinv[node] + b
__global__ __launch_bounds__(256) void k_gather(const float* __restrict__ b,
                                                float* __restrict__ out, int N) {
    int node = blockIdx.x * 8 + (threadIdx.x >> 5);
    if (node >= N) return;
    int lane = threadIdx.x & 31;

    int base = g_off[node];
    int cnt  = g_cnt[node];
    float dd = g_dinv[node];

    float4 acc;
    {
        uint2 u = ((const uint2*)(g_hh + (size_t)node * (NFEAT / 2)))[lane];
        float2 f0 = __half22float2(*(__half2*)&u.x);
        float2 f1 = __half22float2(*(__half2*)&u.y);
        acc = make_float4(f0.x * dd, f0.y * dd, f1.x * dd, f1.y * dd);
    }

    int i = 0;
    for (; i + 4 <= cnt; i += 4) {
        int s0 = g_csr[base + i];
        int s1 = g_csr[base + i + 1];
        int s2 = g_csr[base + i + 2];
        int s3 = g_csr[base + i + 3];
        float w0 = g_dinv[s0], w1 = g_dinv[s1], w2 = g_dinv[s2], w3 = g_dinv[s3];
        uint2 u0 = ((const uint2*)(g_hh + (size_t)s0 * (NFEAT / 2)))[lane];
        uint2 u1 = ((const uint2*)(g_hh + (size_t)s1 * (NFEAT / 2)))[lane];
        uint2 u2 = ((const uint2*)(g_hh + (size_t)s2 * (NFEAT / 2)))[lane];
        uint2 u3 = ((const uint2*)(g_hh + (size_t)s3 * (NFEAT / 2)))[lane];
        float2 a0 = __half22float2(*(__half2*)&u0.x), a1 = __half22float2(*(__half2*)&u0.y);
        float2 c0 = __half22float2(*(__half2*)&u1.x), c1 = __half22float2(*(__half2*)&u1.y);
        float2 d0 = __half22float2(*(__half2*)&u2.x), d1 = __half22float2(*(__half2*)&u2.y);
        float2 e0 = __half22float2(*(__half2*)&u3.x), e1 = __half22float2(*(__half2*)&u3.y);
        acc.x += a0.x * w0 + c0.x * w1 + d0.x * w2 + e0.x * w3;
        acc.y += a0.y * w0 + c0.y * w1 + d0.y * w2 + e0.y * w3;
        acc.z += a1.x * w0 + c1.x * w1 + d1.x * w2 + e1.x * w3;
        acc.w += a1.y * w0 + c1.y * w1 + d1.y * w2 + e1.y * w3;
    }
    for (; i < cnt; i++) {
        int s0 = g_csr[base + i];
        float w0 = g_dinv[s0];
        uint2 u0 = ((const uint2*)(g_hh + (size_t)s0 * (NFEAT / 2)))[lane];
        float2 a0 = __half22float2(*(__half2*)&u0.x), a1 = __half22float2(*(__half2*)&u0.y);
        acc.x += a0.x * w0; acc.y += a0.y * w0;
        acc.z += a1.x * w0; acc.w += a1.y * w0;
    }

    float4 bv = ((const float4*)b)[lane];
    float4 o;
    o.x = bv.x + acc.x * dd;
    o.y = bv.y + acc.y * dd;
    o.z = bv.z + acc.z * dd;
    o.w = bv.w + acc.w * dd;
    ((float4*)(out + (size_t)node * NFEAT))[lane] = o;
}

// ---------------------------------------------------------------------------
extern "C" void kernel_launch(void* const* d_in, const int* in_sizes, int n_in,
                              void* d_out, int out_size) {
    const float* x  = (const float*)d_in[0];
    const int*   ei = (const int*)d_in[1];
    const float* w  = (const float*)d_in[2];
    const float* b  = (const float*)d_in[3];
    float* out = (float*)d_out;

    int N = in_sizes[0] / NFEAT;
    int E = in_sizes[1] / 2;
    int NB = (N + 255) / 256;

    cudaFuncSetAttribute(k_gemm, cudaFuncAttributeMaxDynamicSharedMemorySize,
                         GEMM_SMEM);

    // Detect the capture stream handle (per-thread default under capture).
    cudaStreamCaptureStatus st = cudaStreamCaptureStatusNone;
    cudaStreamIsCapturing(cudaStreamPerThread, &st);
    bool cap = (st == cudaStreamCaptureStatusActive);
    cudaStream_t cs = cap ? cudaStreamPerThread : cudaStreamLegacy;

    // Fork: GEMM on side stream, CSR chain on main stream. Join before gather.
    cudaEventRecord(g_ev_fork, cs);
    cudaStreamWaitEvent(g_s2, g_ev_fork, 0);
    k_gemm<<<(N + 127) / 128, 256, GEMM_SMEM, g_s2>>>(x, w, N);
    cudaEventRecord(g_ev_join, g_s2);

    k_zero_cnt<<<(N + 255) / 256, 256>>>(N);
    if ((E & 3) == 0)
        k_count4<<<(E / 4 + 255) / 256, 256>>>(ei, E);
    else
        k_count1<<<(E + 255) / 256, 256>>>(ei, E);
    k_scan1<<<NB, 256>>>(N);
    k_scan2<<<1, 512>>>(NB);
    k_scan3<<<(N + 255) / 256, 256>>>(N);
    if ((E & 3) == 0)
        k_csr4<<<(E / 4 + 255) / 256, 256>>>(ei, E);
    else
        k_csr1<<<(E + 255) / 256, 256>>>(ei, E);

    cudaStreamWaitEvent(cs, g_ev_join, 0);
    if (!cap)
        cudaStreamWaitEvent(cudaStreamPerThread, g_ev_join, 0);
    k_gather<<<(N + 7) / 8, 256>>>(b, out, N);
}

// round 13
// speedup vs baseline: 1.3667x; 1.0068x over previous
#include <cuda_runtime.h>
#include <cuda_fp16.h>
#include <cstdint>

#define NNODES_MAX 100000
#define NEDGES_MAX 2000000
#define NFEAT 128

// Scratch (allocation-free rule: __device__ globals)
__device__ __half2 g_hh[(size_t)NNODES_MAX * (NFEAT / 2)];  // h = x@W (UNscaled), fp16
__device__ float g_dinv[NNODES_MAX];
__device__ int   g_cnt[NNODES_MAX];
__device__ int   g_scan[NNODES_MAX];
__device__ int   g_part[512];
__device__ int   g_off[NNODES_MAX];
__device__ int   g_cursor[NNODES_MAX];
__device__ int   g_csr[NEDGES_MAX];

// ---------------------------------------------------------------------------
__global__ void k_zero_cnt(int n) {
    int i = blockIdx.x * blockDim.x + threadIdx.x;
    if (i < n) g_cnt[i] = 0;
}

// ---------------------------------------------------------------------------
// Fused GEMM + edge-count. Blocks [0, gemmBlocks) run the tensor-core GEMM
// h = x @ W; blocks [gemmBlocks, gridDim) grid-stride the dst-degree count.
// The two are data-independent; fusing lets the HW overlap them in one launch.
#define XS_STRIDE 136
#define GEMM_SMEM (2 * 128 * XS_STRIDE * (int)sizeof(__half))

__global__ __launch_bounds__(256) void k_gemm_count(
        const float* __restrict__ X, const float* __restrict__ W, int M,
        const int* __restrict__ ei, int E, int gemmBlocks) {
    if (blockIdx.x >= gemmBlocks) {
        // ---- count body: 4 edges/thread via int4, grid-stride ----
        int nb = gridDim.x - gemmBlocks;
        int e4_total = E >> 2;
        for (int e4 = (blockIdx.x - gemmBlocks) * blockDim.x + threadIdx.x;
             e4 < e4_total; e4 += nb * blockDim.x) {
            int4 d = ((const int4*)(ei + E))[e4];
            atomicAdd(&g_cnt[d.x], 1);
            atomicAdd(&g_cnt[d.y], 1);
            atomicAdd(&g_cnt[d.z], 1);
            atomicAdd(&g_cnt[d.w], 1);
        }
        // tail (E % 4) handled by first threads of first count block
        if (blockIdx.x == gemmBlocks) {
            int tail = E & 3;
            if ((int)threadIdx.x < tail)
                atomicAdd(&g_cnt[ei[E + (E & ~3) + threadIdx.x]], 1);
        }
        return;
    }

    // ---- GEMM body ----
    extern __shared__ __half smem[];
    __half* Xs = smem;                       // [128][136]
    __half* Wh = smem + 128 * XS_STRIDE;     // [128][136]

    int tid = threadIdx.x;
    int m0  = blockIdx.x * 128;

#pragma unroll
    for (int j = 0; j < 16; j++) {
        int idx = tid + j * 256;
        int r   = idx >> 5;
        int c4  = idx & 31;
        float4 v = make_float4(0.f, 0.f, 0.f, 0.f);
        int gr = m0 + r;
        if (gr < M)
            v = *(const float4*)(X + (size_t)gr * NFEAT + c4 * 4);
        __half2 h0 = __floats2half2_rn(v.x, v.y);
        __half2 h1 = __floats2half2_rn(v.z, v.w);
        uint2 u; u.x = *(unsigned*)&h0; u.y = *(unsigned*)&h1;
        *(uint2*)(Xs + r * XS_STRIDE + c4 * 4) = u;
    }
#pragma unroll
    for (int j = 0; j < 16; j++) {
        int idx = tid + j * 256;
        int r   = idx >> 5;
        int c4  = idx & 31;
        float4 v = *(const float4*)(W + (size_t)r * NFEAT + c4 * 4);
        __half2 h0 = __floats2half2_rn(v.x, v.y);
        __half2 h1 = __floats2half2_rn(v.z, v.w);
        uint2 u; u.x = *(unsigned*)&h0; u.y = *(unsigned*)&h1;
        *(uint2*)(Wh + r * XS_STRIDE + c4 * 4) = u;
    }
    __syncthreads();

    int lane = tid & 31;
    int wrp  = tid >> 5;
    int mrow = wrp * 16;

    float acc[16][4];
#pragma unroll
    for (int i = 0; i < 16; i++)
#pragma unroll
        for (int j = 0; j < 4; j++) acc[i][j] = 0.f;

    unsigned xs_base = (unsigned)__cvta_generic_to_shared(Xs);
    unsigned wh_base = (unsigned)__cvta_generic_to_shared(Wh);

#pragma unroll
    for (int kt = 0; kt < 8; kt++) {
        int k0 = kt * 16;
        unsigned a_addr = xs_base +
            (((mrow + (lane & 15)) * XS_STRIDE + k0 + (lane >> 4) * 8) << 1);
        unsigned a0, a1, a2, a3;
        asm volatile("ldmatrix.sync.aligned.m8n8.x4.shared.b16 {%0,%1,%2,%3}, [%4];"
                     : "=r"(a0), "=r"(a1), "=r"(a2), "=r"(a3) : "r"(a_addr));

#pragma unroll
        for (int nt2 = 0; nt2 < 8; nt2++) {
            int n0 = nt2 * 16;
            unsigned b_addr = wh_base +
                (((k0 + (lane & 15)) * XS_STRIDE + n0 + (lane >> 4) * 8) << 1);
            unsigned b0, b1, b2, b3;
            asm volatile("ldmatrix.sync.aligned.m8n8.x4.trans.shared.b16 {%0,%1,%2,%3}, [%4];"
                         : "=r"(b0), "=r"(b1), "=r"(b2), "=r"(b3) : "r"(b_addr));

            asm volatile("mma.sync.aligned.m16n8k16.row.col.f32.f16.f16.f32 "
                         "{%0,%1,%2,%3}, {%4,%5,%6,%7}, {%8,%9}, {%0,%1,%2,%3};"
                         : "+f"(acc[2 * nt2][0]), "+f"(acc[2 * nt2][1]),
                           "+f"(acc[2 * nt2][2]), "+f"(acc[2 * nt2][3])
                         : "r"(a0), "r"(a1), "r"(a2), "r"(a3), "r"(b0), "r"(b1));
            asm volatile("mma.sync.aligned.m16n8k16.row.col.f32.f16.f16.f32 "
                         "{%0,%1,%2,%3}, {%4,%5,%6,%7}, {%8,%9}, {%0,%1,%2,%3};"
                         : "+f"(acc[2 * nt2 + 1][0]), "+f"(acc[2 * nt2 + 1][1]),
                           "+f"(acc[2 * nt2 + 1][2]), "+f"(acc[2 * nt2 + 1][3])
                         : "r"(a0), "r"(a1), "r"(a2), "r"(a3), "r"(b2), "r"(b3));
        }
    }

    int g = lane >> 2, t = lane & 3;
    int r0 = m0 + mrow + g;
    int r1 = r0 + 8;
#pragma unroll
    for (int nt = 0; nt < 16; nt++) {
        if (r0 < M)
            g_hh[(size_t)r0 * (NFEAT / 2) + nt * 4 + t] =
                __floats2half2_rn(acc[nt][0], acc[nt][1]);
        if (r1 < M)
            g_hh[(size_t)r1 * (NFEAT / 2) + nt * 4 + t] =
                __floats2half2_rn(acc[nt][2], acc[nt][3]);
    }
}

// ---------------------------------------------------------------------------
// Warp-shuffle scans
__global__ void k_scan1(int n) {
    __shared__ int ws[8];
    int t = threadIdx.x, lane = t & 31, wid = t >> 5;
    int i = blockIdx.x * 256 + t;
    int x = (i < n) ? g_cnt[i] : 0;
#pragma unroll
    for (int ofs = 1; ofs < 32; ofs <<= 1) {
        int y = __shfl_up_sync(0xffffffffu, x, ofs);
        if (lane >= ofs) x += y;
    }
    if (lane == 31) ws[wid] = x;
    __syncthreads();
    if (wid == 0) {
        int y = (lane < 8) ? ws[lane] : 0;
#pragma unroll
        for (int ofs = 1; ofs < 8; ofs <<= 1) {
            int z = __shfl_up_sync(0xffffffffu, y, ofs);
            if (lane >= ofs) y += z;
        }
        if (lane < 8) ws[lane] = y;
    }
    __syncthreads();
    int incl = x + (wid > 0 ? ws[wid - 1] : 0);
    if (i < n) g_scan[i] = incl;
    if (t == 255) g_part[blockIdx.x] = incl;
}

__global__ void k_scan2(int nb) {
    __shared__ int ws[16];
    int t = threadIdx.x, lane = t & 31, wid = t >> 5;
    int x = (t < nb) ? g_part[t] : 0;
#pragma unroll
    for (int ofs = 1; ofs < 32; ofs <<= 1) {
        int y = __shfl_up_sync(0xffffffffu, x, ofs);
        if (lane >= ofs) x += y;
    }
    if (lane == 31) ws[wid] = x;
    __syncthreads();
    if (wid == 0) {
        int y = (lane < 16) ? ws[lane] : 0;
#pragma unroll
        for (int ofs = 1; ofs < 16; ofs <<= 1) {
            int z = __shfl_up_sync(0xffffffffu, y, ofs);
            if (lane >= ofs) y += z;
        }
        if (lane < 16) ws[lane] = y;
    }
    __syncthreads();
    int incl = x + (wid > 0 ? ws[wid - 1] : 0);
    if (t < nb) g_part[t] = incl;
}

// scan3 + dinv fused (both read g_cnt)
__global__ void k_scan3(int n) {
    int i = blockIdx.x * blockDim.x + threadIdx.x;
    if (i >= n) return;
    int b = i >> 8;
    int c = g_cnt[i];
    int off = g_scan[i] - c + (b > 0 ? g_part[b - 1] : 0);
    g_off[i] = off;
    g_cursor[i] = off;
    g_dinv[i] = rsqrtf((float)c + 1.0f);
}

__global__ void k_csr4(const int* __restrict__ ei, int E) {
    int e4 = blockIdx.x * blockDim.x + threadIdx.x;
    if (e4 * 4 >= E) return;
    int4 s = ((const int4*)ei)[e4];
    int4 d = ((const int4*)(ei + E))[e4];
    g_csr[atomicAdd(&g_cursor[d.x], 1)] = s.x;
    g_csr[atomicAdd(&g_cursor[d.y], 1)] = s.y;
    g_csr[atomicAdd(&g_cursor[d.z], 1)] = s.z;
    g_csr[atomicAdd(&g_cursor[d.w], 1)] = s.w;
}
__global__ void k_csr1(const int* __restrict__ ei, int E) {
    int e = blockIdx.x * blockDim.x + threadIdx.x;
    if (e >= E) return;
    g_csr[atomicAdd(&g_cursor[ei[E + e]], 1)] = ei[e];
}

// ---------------------------------------------------------------------------
// Gather: one warp per dst node; h unscaled -> apply dinv[src] per edge.
// out = (sum_src dinv[s]*h[s] + dinv[node]*h[node]) * dinv[node] + b
__global__ __launch_bounds__(256) void k_gather(const float* __restrict__ b,
                                                float* __restrict__ out, int N) {
    int node = blockIdx.x * 8 + (threadIdx.x >> 5);
    if (node >= N) return;
    int lane = threadIdx.x & 31;

    int base = g_off[node];
    int cnt  = g_cnt[node];
    float dd = g_dinv[node];

    float4 acc;
    {
        uint2 u = ((const uint2*)(g_hh + (size_t)node * (NFEAT / 2)))[lane];
        float2 f0 = __half22float2(*(__half2*)&u.x);
        float2 f1 = __half22float2(*(__half2*)&u.y);
        acc = make_float4(f0.x * dd, f0.y * dd, f1.x * dd, f1.y * dd);
    }

    int i = 0;
    for (; i + 4 <= cnt; i += 4) {
        int s0 = g_csr[base + i];
        int s1 = g_csr[base + i + 1];
        int s2 = g_csr[base + i + 2];
        int s3 = g_csr[base + i + 3];
        float w0 = g_dinv[s0], w1 = g_dinv[s1], w2 = g_dinv[s2], w3 = g_dinv[s3];
        uint2 u0 = ((const uint2*)(g_hh + (size_t)s0 * (NFEAT / 2)))[lane];
        uint2 u1 = ((const uint2*)(g_hh + (size_t)s1 * (NFEAT / 2)))[lane];
        uint2 u2 = ((const uint2*)(g_hh + (size_t)s2 * (NFEAT / 2)))[lane];
        uint2 u3 = ((const uint2*)(g_hh + (size_t)s3 * (NFEAT / 2)))[lane];
        float2 a0 = __half22float2(*(__half2*)&u0.x), a1 = __half22float2(*(__half2*)&u0.y);
        float2 c0 = __half22float2(*(__half2*)&u1.x), c1 = __half22float2(*(__half2*)&u1.y);
        float2 d0 = __half22float2(*(__half2*)&u2.x), d1 = __half22float2(*(__half2*)&u2.y);
        float2 e0 = __half22float2(*(__half2*)&u3.x), e1 = __half22float2(*(__half2*)&u3.y);
        acc.x += a0.x * w0 + c0.x * w1 + d0.x * w2 + e0.x * w3;
        acc.y += a0.y * w0 + c0.y * w1 + d0.y * w2 + e0.y * w3;
        acc.z += a1.x * w0 + c1.x * w1 + d1.x * w2 + e1.x * w3;
        acc.w += a1.y * w0 + c1.y * w1 + d1.y * w2 + e1.y * w3;
    }
    for (; i < cnt; i++) {
        int s0 = g_csr[base + i];
        float w0 = g_dinv[s0];
        uint2 u0 = ((const uint2*)(g_hh + (size_t)s0 * (NFEAT / 2)))[lane];
        float2 a0 = __half22float2(*(__half2*)&u0.x), a1 = __half22float2(*(__half2*)&u0.y);
        acc.x += a0.x * w0; acc.y += a0.y * w0;
        acc.z += a1.x * w0; acc.w += a1.y * w0;
    }

    float4 bv = ((const float4*)b)[lane];
    float4 o;
    o.x = bv.x + acc.x * dd;
    o.y = bv.y + acc.y * dd;
    o.z = bv.z + acc.z * dd;
    o.w = bv.w + acc.w * dd;
    ((float4*)(out + (size_t)node * NFEAT))[lane] = o;
}

// ---------------------------------------------------------------------------
extern "C" void kernel_launch(void* const* d_in, const int* in_sizes, int n_in,
                              void* d_out, int out_size) {
    const float* x  = (const float*)d_in[0];
    const int*   ei = (const int*)d_in[1];
    const float* w  = (const float*)d_in[2];
    const float* b  = (const float*)d_in[3];
    float* out = (float*)d_out;

    int N = in_sizes[0] / NFEAT;
    int E = in_sizes[1] / 2;
    int NB = (N + 255) / 256;

    cudaFuncSetAttribute(k_gemm_count,
                         cudaFuncAttributeMaxDynamicSharedMemorySize, GEMM_SMEM);

    int gemmBlocks  = (N + 127) / 128;
    int countBlocks = 400;

    k_zero_cnt<<<(N + 255) / 256, 256>>>(N);
    k_gemm_count<<<gemmBlocks + countBlocks, 256, GEMM_SMEM>>>(x, w, N, ei, E,
                                                               gemmBlocks);
    k_scan1<<<NB, 256>>>(N);
    k_scan2<<<1, 512>>>(NB);
    k_scan3<<<(N + 255) / 256, 256>>>(N);
    if ((E & 3) == 0)
        k_csr4<<<(E / 4 + 255) / 256, 256>>>(ei, E);
    else
        k_csr1<<<(E + 255) / 256, 256>>>(ei, E);
    k_gather<<<(N + 7) / 8, 256>>>(b, out, N);
}